// round 1
// baseline (speedup 1.0000x reference)
#include <cuda_runtime.h>
#include <cstddef>

#define SQ    1024      // seq length S (== MAX_POS)
#define DH    64        // head dim
#define EMB   1024      // embed size E = H*D
#define MROWS 2047      // 2*MAX_POS - 1 rows of position embeddings
#define NHEAD 32        // B*H global heads

// Scratch for R = P @ W  (8.4 MB) — static device global (no runtime alloc).
__device__ float g_R[(size_t)MROWS * EMB];

// ---------------------------------------------------------------------------
// GEMM1: R[m,n] = sum_k P[m,k] * W[k,n]   (M=2047, N=1024, K=1024)
// 64x64 block tile, BK=16, 256 threads, 4x4 micro-tile per thread.
// ---------------------------------------------------------------------------
__global__ __launch_bounds__(256)
void gemm1_kernel(const float* __restrict__ P, const float* __restrict__ W) {
    __shared__ float As[16][68];   // [k][m], padded
    __shared__ float Bs[16][68];   // [k][n], padded

    const int tid = threadIdx.x;
    const int tx  = tid & 15;      // n group
    const int ty  = tid >> 4;      // m group
    const int m0  = blockIdx.y * 64;
    const int n0  = blockIdx.x * 64;

    const int arow = tid >> 2;           // 0..63
    const int akc  = (tid & 3) << 2;     // 0,4,8,12
    const int brow = tid >> 4;           // 0..15
    const int bnc  = (tid & 15) << 2;    // 0..60

    float c[4][4] = {};

    for (int k0 = 0; k0 < EMB; k0 += 16) {
        float4 av = make_float4(0.f, 0.f, 0.f, 0.f);
        if (m0 + arow < MROWS)
            av = *reinterpret_cast<const float4*>(
                P + (size_t)(m0 + arow) * EMB + k0 + akc);
        As[akc + 0][arow] = av.x;
        As[akc + 1][arow] = av.y;
        As[akc + 2][arow] = av.z;
        As[akc + 3][arow] = av.w;

        *reinterpret_cast<float4*>(&Bs[brow][bnc]) =
            *reinterpret_cast<const float4*>(
                W + (size_t)(k0 + brow) * EMB + n0 + bnc);
        __syncthreads();

#pragma unroll
        for (int k = 0; k < 16; ++k) {
            const float4 a4 = *reinterpret_cast<const float4*>(&As[k][ty << 2]);
            const float4 b4 = *reinterpret_cast<const float4*>(&Bs[k][tx << 2]);
            const float aa[4] = {a4.x, a4.y, a4.z, a4.w};
            const float bb[4] = {b4.x, b4.y, b4.z, b4.w};
#pragma unroll
            for (int i = 0; i < 4; ++i)
#pragma unroll
                for (int j = 0; j < 4; ++j)
                    c[i][j] = fmaf(aa[i], bb[j], c[i][j]);
        }
        __syncthreads();
    }

#pragma unroll
    for (int i = 0; i < 4; ++i) {
        const int m = m0 + (ty << 2) + i;
        if (m < MROWS)
            *reinterpret_cast<float4*>(
                g_R + (size_t)m * EMB + n0 + (tx << 2)) =
                make_float4(c[i][0], c[i][1], c[i][2], c[i][3]);
    }
}

// ---------------------------------------------------------------------------
// GEMM2 (fused banded score + relative shift):
//   out[g, i, j] = sum_d Q[g, i, d] * R[1023 - i + j, (g>>1)*64 + d]
// 64(i) x 64(j) tile per block, 128 threads, 8x4 micro-tile, K = 64 in smem.
// Tile needs R rows m in [m_base, m_base+126], m_base = 960 - i0 + j0,
// always within [0, 2046] -> no clamping, no wasted FLOPs.
// ---------------------------------------------------------------------------
__global__ __launch_bounds__(128)
void gemm2_kernel(const float* __restrict__ Q, float* __restrict__ out) {
    __shared__ float Qs[64][64];    // [d][i_local]
    __shared__ float Rs[64][128];   // [d][t],  t = 63 - ti + tj  (0..126 valid)

    const int tid = threadIdx.x;
    const int tx  = tid & 15;       // j group (4 cols)
    const int ty  = tid >> 4;       // i group (8 rows), 0..7
    const int j0  = blockIdx.x * 64;
    const int i0  = blockIdx.y * 64;
    const int g   = blockIdx.z;
    const int he  = g >> 1;
    const int m_base = (SQ - 1) - (i0 + 63) + j0;   // 960 - i0 + j0

    // Load Q tile [64 rows x 64 d], transposed -> Qs[d][r]
    for (int idx = tid; idx < 64 * 16; idx += 128) {
        const int r  = idx >> 4;
        const int dc = (idx & 15) << 2;
        const float4 v = *reinterpret_cast<const float4*>(
            Q + ((size_t)g * SQ + (i0 + r)) * DH + dc);
        Qs[dc + 0][r] = v.x;
        Qs[dc + 1][r] = v.y;
        Qs[dc + 2][r] = v.z;
        Qs[dc + 3][r] = v.w;
    }
    // Load R band [127 rows x 64 d], transposed -> Rs[d][t]
    const float* Rp = g_R + (size_t)he * DH;
    for (int idx = tid; idx < 127 * 16; idx += 128) {
        const int t  = idx >> 4;
        const int dc = (idx & 15) << 2;
        const float4 v = *reinterpret_cast<const float4*>(
            Rp + (size_t)(m_base + t) * EMB + dc);
        Rs[dc + 0][t] = v.x;
        Rs[dc + 1][t] = v.y;
        Rs[dc + 2][t] = v.z;
        Rs[dc + 3][t] = v.w;
    }
    __syncthreads();

    float c[8][4] = {};
    const int ibase = ty << 3;                       // local i start
    const int jbase = tx << 2;                       // local j start
    const int tb    = 56 - (ty << 3) + (tx << 2);    // = 63-(ibase+7)+jbase, %4==0
    // t = tb + (7 - ii) + jj,  b-index = 7 - ii + jj in [0, 10]

#pragma unroll 4
    for (int k = 0; k < 64; ++k) {
        float a[8];
        const float4 a0 = *reinterpret_cast<const float4*>(&Qs[k][ibase]);
        const float4 a1 = *reinterpret_cast<const float4*>(&Qs[k][ibase + 4]);
        a[0] = a0.x; a[1] = a0.y; a[2] = a0.z; a[3] = a0.w;
        a[4] = a1.x; a[5] = a1.y; a[6] = a1.z; a[7] = a1.w;

        float b[12];
        const float4 b0 = *reinterpret_cast<const float4*>(&Rs[k][tb]);
        const float4 b1 = *reinterpret_cast<const float4*>(&Rs[k][tb + 4]);
        const float4 b2 = *reinterpret_cast<const float4*>(&Rs[k][tb + 8]);
        b[0] = b0.x; b[1]  = b0.y; b[2]  = b0.z; b[3]  = b0.w;
        b[4] = b1.x; b[5]  = b1.y; b[6]  = b1.z; b[7]  = b1.w;
        b[8] = b2.x; b[9]  = b2.y; b[10] = b2.z; b[11] = b2.w;

#pragma unroll
        for (int ii = 0; ii < 8; ++ii)
#pragma unroll
            for (int jj = 0; jj < 4; ++jj)
                c[ii][jj] = fmaf(a[ii], b[7 - ii + jj], c[ii][jj]);
    }

    const size_t obase = (size_t)g * SQ * SQ;
#pragma unroll
    for (int ii = 0; ii < 8; ++ii) {
        *reinterpret_cast<float4*>(
            out + obase + (size_t)(i0 + ibase + ii) * SQ + j0 + jbase) =
            make_float4(c[ii][0], c[ii][1], c[ii][2], c[ii][3]);
    }
}

// ---------------------------------------------------------------------------
// Launch: inputs in metadata order: query [2,16,1024,64], position_embeddings
// [2047,1024], dense_kernel [1024,1024]. Output float32 [2,16,1024,1024].
// The gather is the identity (S == MAX_POS), so GEMM1 consumes P directly.
// ---------------------------------------------------------------------------
extern "C" void kernel_launch(void* const* d_in, const int* in_sizes, int n_in,
                              void* d_out, int out_size) {
    const float* query = (const float*)d_in[0];
    const float* posem = (const float*)d_in[1];
    const float* dense = (const float*)d_in[2];
    float* out = (float*)d_out;

    (void)in_sizes; (void)n_in; (void)out_size;

    // GEMM1: R = P @ W
    gemm1_kernel<<<dim3(EMB / 64, (MROWS + 63) / 64), 256>>>(posem, dense);
    // GEMM2: banded score with fused relative shift
    gemm2_kernel<<<dim3(SQ / 64, SQ / 64, NHEAD), 128>>>(query, out);
}

// round 2
// speedup vs baseline: 1.0867x; 1.0867x over previous
#include <cuda_runtime.h>
#include <cstddef>

#define SQ    1024
#define DH    64
#define EMB   1024
#define MROWS 2047
#define NHEAD 32

// Scratch for R = P @ W  (8.4 MB)
__device__ float g_R[(size_t)MROWS * EMB];

// ---------------------------------------------------------------------------
// GEMM1: R[m,n] = sum_k P[m,k] * W[k,n]   (M=2047, N=1024, K=1024)
// 64(m) x 128(n) tile, BK=8 double-buffered, 128 threads, 8x8 micro-tile.
// As is stored [k][m] with XOR swizzle for conflict-free transpose + reads.
// ---------------------------------------------------------------------------
__global__ __launch_bounds__(128)
void gemm1_kernel(const float* __restrict__ P, const float* __restrict__ W) {
    __shared__ float As[2][8][64];    // [k][m] swizzled
    __shared__ float Bs[2][8][128];   // [k][n]

    const int tid = threadIdx.x;
    const int n0  = blockIdx.x * 128;
    const int m0  = blockIdx.y * 64;

    const int am = tid >> 1;            // 0..63
    const int ak = (tid & 1) << 2;      // 0 or 4
    const bool a_ok = (m0 + am) < MROWS;

    const int ty = tid >> 4;            // 0..7
    const int tx = tid & 15;            // 0..15
    const int ib = ty << 3;
    const int jb = tx << 3;
    const int ga = ib >> 2;             // a group base (even)

    float4 aReg;
    float4 bReg[2];

    // ---- prologue: load tile 0 into buffer 0 ----
    aReg = make_float4(0.f, 0.f, 0.f, 0.f);
    if (a_ok) aReg = *(const float4*)(P + (size_t)(m0 + am) * EMB + ak);
#pragma unroll
    for (int r = 0; r < 2; ++r) {
        const int idx = tid + (r << 7);
        const int bk = idx >> 5, bn = (idx & 31) << 2;
        bReg[r] = *(const float4*)(W + (size_t)bk * EMB + n0 + bn);
    }
#pragma unroll
    for (int q = 0; q < 4; ++q) {
        const int k = ak + q;
        As[0][k][((((am >> 2) ^ k) & 15) << 2) | (am & 3)] = ((const float*)&aReg)[q];
    }
#pragma unroll
    for (int r = 0; r < 2; ++r) {
        const int idx = tid + (r << 7);
        *(float4*)&Bs[0][idx >> 5][(idx & 31) << 2] = bReg[r];
    }
    __syncthreads();

    float acc[8][8] = {};

    const int NT = EMB / 8;   // 128 k-tiles
    for (int t = 0; t < NT; ++t) {
        const int cur = t & 1;
        if (t + 1 < NT) {
            const int k0n = (t + 1) << 3;
            aReg = make_float4(0.f, 0.f, 0.f, 0.f);
            if (a_ok) aReg = *(const float4*)(P + (size_t)(m0 + am) * EMB + k0n + ak);
#pragma unroll
            for (int r = 0; r < 2; ++r) {
                const int idx = tid + (r << 7);
                const int bk = idx >> 5, bn = (idx & 31) << 2;
                bReg[r] = *(const float4*)(W + (size_t)(k0n + bk) * EMB + n0 + bn);
            }
        }
#pragma unroll
        for (int k = 0; k < 8; ++k) {
            const float4 a0 = *(const float4*)&As[cur][k][(((ga    ) ^ k) & 15) << 2];
            const float4 a1 = *(const float4*)&As[cur][k][(((ga + 1) ^ k) & 15) << 2];
            const float4 b0 = *(const float4*)&Bs[cur][k][jb];
            const float4 b1 = *(const float4*)&Bs[cur][k][jb + 4];
            const float a[8] = {a0.x,a0.y,a0.z,a0.w,a1.x,a1.y,a1.z,a1.w};
            const float b[8] = {b0.x,b0.y,b0.z,b0.w,b1.x,b1.y,b1.z,b1.w};
#pragma unroll
            for (int i = 0; i < 8; ++i)
#pragma unroll
                for (int j = 0; j < 8; ++j)
                    acc[i][j] = fmaf(a[i], b[j], acc[i][j]);
        }
        if (t + 1 < NT) {
            const int nxt = cur ^ 1;
#pragma unroll
            for (int q = 0; q < 4; ++q) {
                const int k = ak + q;
                As[nxt][k][((((am >> 2) ^ k) & 15) << 2) | (am & 3)] = ((const float*)&aReg)[q];
            }
#pragma unroll
            for (int r = 0; r < 2; ++r) {
                const int idx = tid + (r << 7);
                *(float4*)&Bs[nxt][idx >> 5][(idx & 31) << 2] = bReg[r];
            }
            __syncthreads();
        }
    }

#pragma unroll
    for (int i = 0; i < 8; ++i) {
        const int m = m0 + ib + i;
        if (m < MROWS) {
            *(float4*)(g_R + (size_t)m * EMB + n0 + jb) =
                make_float4(acc[i][0], acc[i][1], acc[i][2], acc[i][3]);
            *(float4*)(g_R + (size_t)m * EMB + n0 + jb + 4) =
                make_float4(acc[i][4], acc[i][5], acc[i][6], acc[i][7]);
        }
    }
}

// ---------------------------------------------------------------------------
// GEMM2 on diagonals: c = j - i, R row = 1023 + c (depends only on c).
//   out[g, i, i+c] = sum_d Q[g,i,d] * R[1023+c, (g>>1)*64 + d]
// 128(i) x 128(c) tile per block, K=64 in two 32-deep phases, 256 threads,
// 8x8 micro-tile. 9 c-tiles cover all valid c per i-tile (12.5% tile waste).
// Per-element j-guard on store; each output written exactly once.
// ---------------------------------------------------------------------------
__global__ __launch_bounds__(256)
void gemm2_kernel(const float* __restrict__ Q, float* __restrict__ out) {
    __shared__ float Qs[32][128];   // [d][i] swizzled
    __shared__ float Rs[32][128];   // [d][c] swizzled

    const int tid = threadIdx.x;
    const int g   = blockIdx.z;
    const int he  = g >> 1;
    const int i0  = blockIdx.y << 7;
    const int c0  = (((int)blockIdx.x) - 1) * 128 - i0;
    const int t0  = 1023 + c0;                 // R row base, may need clamping

    const int ty = tid >> 4, tx = tid & 15;
    const int ib = ty << 3,  cb = tx << 3;
    const int ga = ib >> 2;                    // 0..30 even
    const int gb = cb >> 2;

    float acc[8][8] = {};

    for (int ph = 0; ph < 2; ++ph) {
        const int d0 = ph << 5;
        if (ph) __syncthreads();               // everyone done reading phase 0

        // load Q slab: 128 i x 32 d  (1024 float4, 4 per thread)
#pragma unroll
        for (int r = 0; r < 4; ++r) {
            const int idx = tid + (r << 8);
            const int row = idx >> 3;          // i local
            const int dc  = (idx & 7) << 2;    // d local base
            const float4 v = *(const float4*)(
                Q + ((size_t)g * SQ + i0 + row) * DH + d0 + dc);
#pragma unroll
            for (int q = 0; q < 4; ++q) {
                const int d = dc + q;
                Qs[d][((((row >> 2) ^ d) & 31) << 2) | (row & 3)] =
                    ((const float*)&v)[q];
            }
        }
        // load R slab: 128 c x 32 d (rows clamped; clamped rows only feed
        // accumulators whose j is out of range and never stored)
#pragma unroll
        for (int r = 0; r < 4; ++r) {
            const int idx = tid + (r << 8);
            const int cl  = idx >> 3;
            const int dc  = (idx & 7) << 2;
            int t = t0 + cl;
            t = t < 0 ? 0 : (t > 2046 ? 2046 : t);
            const float4 v = *(const float4*)(
                g_R + (size_t)t * EMB + he * DH + d0 + dc);
#pragma unroll
            for (int q = 0; q < 4; ++q) {
                const int d = dc + q;
                Rs[d][((((cl >> 2) ^ d) & 31) << 2) | (cl & 3)] =
                    ((const float*)&v)[q];
            }
        }
        __syncthreads();

#pragma unroll 8
        for (int d = 0; d < 32; ++d) {
            const float4 a0 = *(const float4*)&Qs[d][(((ga    ) ^ d) & 31) << 2];
            const float4 a1 = *(const float4*)&Qs[d][(((ga + 1) ^ d) & 31) << 2];
            const float4 b0 = *(const float4*)&Rs[d][(((gb    ) ^ d) & 31) << 2];
            const float4 b1 = *(const float4*)&Rs[d][(((gb + 1) ^ d) & 31) << 2];
            const float a[8] = {a0.x,a0.y,a0.z,a0.w,a1.x,a1.y,a1.z,a1.w};
            const float b[8] = {b0.x,b0.y,b0.z,b0.w,b1.x,b1.y,b1.z,b1.w};
#pragma unroll
            for (int i = 0; i < 8; ++i)
#pragma unroll
                for (int j = 0; j < 8; ++j)
                    acc[i][j] = fmaf(a[i], b[j], acc[i][j]);
        }
    }

    // store: j = i + c, guard 0 <= j < 1024
#pragma unroll
    for (int ii = 0; ii < 8; ++ii) {
        const int i = i0 + ib + ii;
        const int jbase = i + c0 + cb;
        float* orow = out + ((size_t)g << 20) + ((size_t)i << 10);
#pragma unroll
        for (int jj = 0; jj < 8; ++jj) {
            const int j = jbase + jj;
            if ((unsigned)j < 1024u) orow[j] = acc[ii][jj];
        }
    }
}

// ---------------------------------------------------------------------------
extern "C" void kernel_launch(void* const* d_in, const int* in_sizes, int n_in,
                              void* d_out, int out_size) {
    const float* query = (const float*)d_in[0];
    const float* posem = (const float*)d_in[1];
    const float* dense = (const float*)d_in[2];
    float* out = (float*)d_out;
    (void)in_sizes; (void)n_in; (void)out_size;

    gemm1_kernel<<<dim3(EMB / 128, 32), 128>>>(posem, dense);
    gemm2_kernel<<<dim3(9, SQ / 128, NHEAD), 256>>>(query, out);
}

// round 4
// speedup vs baseline: 2.0824x; 1.9163x over previous
#include <cuda_runtime.h>
#include <cuda_bf16.h>
#include <cstdint>
#include <cstddef>

// ===================== portable tensor-core helpers (sm_80+) ================
__device__ __forceinline__ uint32_t smem_u32(const void* p) {
    uint32_t a;
    asm("{ .reg .u64 t; cvta.to.shared.u64 t, %1; cvt.u32.u64 %0, t; }"
        : "=r"(a) : "l"(p));
    return a;
}
#define CP16(sm, gp) \
    asm volatile("cp.async.cg.shared.global [%0], [%1], 16;" :: "r"(sm), "l"(gp))
#define CP_COMMIT() asm volatile("cp.async.commit_group;" ::: "memory")
#define CP_WAIT(n)  asm volatile("cp.async.wait_group %0;" :: "n"(n) : "memory")

#define LDSM_X4(r0, r1, r2, r3, addr) \
    asm volatile("ldmatrix.sync.aligned.m8n8.x4.shared.b16 {%0,%1,%2,%3}, [%4];" \
                 : "=r"(r0), "=r"(r1), "=r"(r2), "=r"(r3) : "r"(addr))
#define LDSM_X2(r0, r1, addr) \
    asm volatile("ldmatrix.sync.aligned.m8n8.x2.shared.b16 {%0,%1}, [%2];" \
                 : "=r"(r0), "=r"(r1) : "r"(addr))
#define MMA16816(c, a, b) \
    asm volatile("mma.sync.aligned.m16n8k16.row.col.f32.bf16.bf16.f32 " \
                 "{%0,%1,%2,%3}, {%4,%5,%6,%7}, {%8,%9}, {%0,%1,%2,%3};" \
                 : "+f"((c)[0]), "+f"((c)[1]), "+f"((c)[2]), "+f"((c)[3]) \
                 : "r"((a)[0]), "r"((a)[1]), "r"((a)[2]), "r"((a)[3]), \
                   "r"((b)[0]), "r"((b)[1]))

// ===================== scratch (bf16 split operands) ========================
// Pcat [2048][3072] : A' = [P_hi | P_hi | P_mid]           (row-major)
// Wt   [1024][3072] : B' = [W_hi | W_mid | W_hi]           (N-major)
// Qcat [32*1024][192] : per row [Q_hi | Q_hi | Q_mid]
// Rcat [16 he][2048 t][192] : per (he,t) [R_hi | R_mid | R_hi]
__device__ uint4 g_Pcat[786432];
__device__ uint4 g_Wt[393216];
__device__ uint4 g_Qcat[786432];
__device__ uint4 g_Rcat[786432];

// ===================== split kernels ========================================
__global__ void split_p(const float* __restrict__ P) {
    int idx = blockIdx.x * 256 + threadIdx.x;     // 2048 * 512
    int m = idx >> 9, kp = idx & 511;
    float2 v = make_float2(0.f, 0.f);
    if (m < 2047) v = *(const float2*)(P + (size_t)m * 1024 + 2 * kp);
    __nv_bfloat162 hi, mid;
    hi.x = __float2bfloat16(v.x); hi.y = __float2bfloat16(v.y);
    mid.x = __float2bfloat16(v.x - __bfloat162float(hi.x));
    mid.y = __float2bfloat16(v.y - __bfloat162float(hi.y));
    __nv_bfloat162* dst = (__nv_bfloat162*)g_Pcat + (size_t)m * 1536 + kp;
    dst[0] = hi; dst[512] = hi; dst[1024] = mid;
}

__global__ void split_q(const float* __restrict__ Q) {
    int idx = blockIdx.x * 256 + threadIdx.x;     // 32*1024 * 32
    int gi = idx >> 5, dp = idx & 31;
    float2 v = *(const float2*)(Q + (size_t)gi * 64 + 2 * dp);
    __nv_bfloat162 hi, mid;
    hi.x = __float2bfloat16(v.x); hi.y = __float2bfloat16(v.y);
    mid.x = __float2bfloat16(v.x - __bfloat162float(hi.x));
    mid.y = __float2bfloat16(v.y - __bfloat162float(hi.y));
    __nv_bfloat162* dst = (__nv_bfloat162*)g_Qcat + (size_t)gi * 96 + dp;
    dst[0] = hi; dst[32] = hi; dst[64] = mid;
}

__global__ void split_w(const float* __restrict__ W) {
    __shared__ float t[32][33];
    const int n0 = blockIdx.x * 32, k0 = blockIdx.y * 32;
    const int x = threadIdx.x, y = threadIdx.y;   // (32, 8)
    for (int r = 0; r < 32; r += 8)
        t[y + r][x] = W[(size_t)(k0 + y + r) * 1024 + n0 + x];
    __syncthreads();
    __nv_bfloat16* Wt = (__nv_bfloat16*)g_Wt;
    for (int r = 0; r < 32; r += 8) {
        const float v = t[x][y + r];              // W[k0+x][n0+y+r]
        const int n = n0 + y + r, k = k0 + x;
        const __nv_bfloat16 hi = __float2bfloat16(v);
        const __nv_bfloat16 mid = __float2bfloat16(v - __bfloat162float(hi));
        Wt[(size_t)n * 3072 + k] = hi;
        Wt[(size_t)n * 3072 + 1024 + k] = mid;
        Wt[(size_t)n * 3072 + 2048 + k] = hi;
    }
}

// ===================== common GEMM body =====================================
// CTA tile 128(M) x 128(N), BK=32, 256 threads = 8 warps (2x4),
// warp tile 64x32 via m16n8k16: 4 m-frags x 4 n-frags.
// Smem stage: A[128][40] + B[128][40] bf16 (40-pad => conflict-free ldmatrix).
#define STAGE_ELEMS 10240          // (128*40)*2 arrays
#define STAGE_BYTES 20480

struct Frag { float c[4][4][4]; };  // [mi][ni][4]

__device__ __forceinline__ void mma_tile(const __nv_bfloat16* As,
                                         const __nv_bfloat16* Bs,
                                         int wm, int wn, int lane, Frag& f) {
#pragma unroll
    for (int h = 0; h < 2; ++h) {
        const int k16 = h << 4;
        uint32_t a[4][4], b[4][2];
#pragma unroll
        for (int mi = 0; mi < 4; ++mi) {
            const uint32_t ad = smem_u32(
                As + (wm + mi * 16 + (lane & 15)) * 40 + k16 + ((lane >> 4) << 3));
            LDSM_X4(a[mi][0], a[mi][1], a[mi][2], a[mi][3], ad);
        }
#pragma unroll
        for (int ni = 0; ni < 4; ++ni) {
            const uint32_t bd = smem_u32(
                Bs + (wn + ni * 8 + (lane & 7)) * 40 + k16 + (((lane >> 3) & 1) << 3));
            LDSM_X2(b[ni][0], b[ni][1], bd);
        }
#pragma unroll
        for (int mi = 0; mi < 4; ++mi)
#pragma unroll
            for (int ni = 0; ni < 4; ++ni)
                MMA16816(f.c[mi][ni], a[mi], b[ni]);
    }
}

// ===================== GEMM1: R = P @ W  (M=2048,N=1024,K'=3072) ============
__global__ __launch_bounds__(256) void gemm1_mma() {
    extern __shared__ __nv_bfloat16 sm[];
    const int tid = threadIdx.x, lane = tid & 31, wid = tid >> 5;
    const int wm = (wid >> 2) << 6, wn = (wid & 3) << 5;
    const int m0 = blockIdx.y << 7, n0 = blockIdx.x << 7;

    const __nv_bfloat16* Ag = (const __nv_bfloat16*)g_Pcat;
    const __nv_bfloat16* Bg = (const __nv_bfloat16*)g_Wt;
    __nv_bfloat16* Rc = (__nv_bfloat16*)g_Rcat;

    const int lrow = tid >> 1, lch = (tid & 1) << 4;   // load row / 16-elem chunk
    const uint32_t sA = smem_u32(sm) + (uint32_t)(lrow * 40 + lch) * 2;
    const uint32_t sB = sA + STAGE_BYTES / 2;          // B at +10240 bytes
    const __nv_bfloat16* gA = Ag + (size_t)(m0 + lrow) * 3072 + lch;
    const __nv_bfloat16* gB = Bg + (size_t)(n0 + lrow) * 3072 + lch;

    const int NK = 96;
    // prologue: stage 0
    CP16(sA, gA); CP16(sA + 16, gA + 8);
    CP16(sB, gB); CP16(sB + 16, gB + 8);
    CP_COMMIT();

    Frag f;
#pragma unroll
    for (int mi = 0; mi < 4; ++mi)
#pragma unroll
        for (int ni = 0; ni < 4; ++ni)
#pragma unroll
            for (int r = 0; r < 4; ++r) f.c[mi][ni][r] = 0.f;

    for (int kk = 0; kk < NK; ++kk) {
        if (kk + 1 < NK) {
            const uint32_t off = (uint32_t)(((kk + 1) & 1) * STAGE_BYTES);
            const size_t go = (size_t)(kk + 1) * 32;
            CP16(sA + off, gA + go); CP16(sA + off + 16, gA + go + 8);
            CP16(sB + off, gB + go); CP16(sB + off + 16, gB + go + 8);
            CP_COMMIT();
            CP_WAIT(1);
        } else {
            CP_WAIT(0);
        }
        __syncthreads();
        const __nv_bfloat16* As = sm + (kk & 1) * STAGE_ELEMS;
        mma_tile(As, As + 5120, wm, wn, lane, f);
        __syncthreads();
    }

    // epilogue: fp32 accum -> bf16 hi/mid -> Rcat[he][m][split][64]
#pragma unroll
    for (int mi = 0; mi < 4; ++mi)
#pragma unroll
        for (int ni = 0; ni < 4; ++ni)
#pragma unroll
            for (int r = 0; r < 2; ++r) {
                const int m = m0 + wm + mi * 16 + (lane >> 2) + r * 8;
                const int n = n0 + wn + ni * 8 + ((lane & 3) << 1);
                const float x0 = f.c[mi][ni][r * 2];
                const float x1 = f.c[mi][ni][r * 2 + 1];
                __nv_bfloat162 hi, mid;
                hi.x = __float2bfloat16(x0); hi.y = __float2bfloat16(x1);
                mid.x = __float2bfloat16(x0 - __bfloat162float(hi.x));
                mid.y = __float2bfloat16(x1 - __bfloat162float(hi.y));
                const int he = n >> 6, d = n & 63;
                __nv_bfloat16* p = Rc + ((size_t)(he * 2048 + m)) * 192 + d;
                *(__nv_bfloat162*)(p)       = hi;
                *(__nv_bfloat162*)(p + 64)  = mid;
                *(__nv_bfloat162*)(p + 128) = hi;
            }
}

// ===================== GEMM2: banded score, diagonal form ===================
// out[g, i, i+c] = sum Qcat[g,i,:] . Rcat[he, 1023+c, :]   (K'=192)
__global__ __launch_bounds__(256) void gemm2_mma(float* __restrict__ out) {
    extern __shared__ __nv_bfloat16 sm[];
    const int tid = threadIdx.x, lane = tid & 31, wid = tid >> 5;
    const int wm = (wid >> 2) << 6, wn = (wid & 3) << 5;
    const int g = blockIdx.z, he = g >> 1;
    const int i0 = blockIdx.y << 7;
    const int c0 = ((int)blockIdx.x - 1) * 128 - i0;
    const int t0 = 1023 + c0;

    const __nv_bfloat16* Ag = (const __nv_bfloat16*)g_Qcat;
    const __nv_bfloat16* Bg = (const __nv_bfloat16*)g_Rcat;

    const int lrow = tid >> 1, lch = (tid & 1) << 4;
    const uint32_t sA = smem_u32(sm) + (uint32_t)(lrow * 40 + lch) * 2;
    const uint32_t sB = sA + STAGE_BYTES / 2;
    const __nv_bfloat16* gA = Ag + ((size_t)(g << 10) + i0 + lrow) * 192 + lch;
    int tr = t0 + lrow;                      // clamped rows feed only columns
    tr = tr < 0 ? 0 : (tr > 2046 ? 2046 : tr);   // whose j is out of range
    const __nv_bfloat16* gB = Bg + (size_t)(he * 2048 + tr) * 192 + lch;

    const int NK = 6;
    CP16(sA, gA); CP16(sA + 16, gA + 8);
    CP16(sB, gB); CP16(sB + 16, gB + 8);
    CP_COMMIT();

    Frag f;
#pragma unroll
    for (int mi = 0; mi < 4; ++mi)
#pragma unroll
        for (int ni = 0; ni < 4; ++ni)
#pragma unroll
            for (int r = 0; r < 4; ++r) f.c[mi][ni][r] = 0.f;

    for (int kk = 0; kk < NK; ++kk) {
        if (kk + 1 < NK) {
            const uint32_t off = (uint32_t)(((kk + 1) & 1) * STAGE_BYTES);
            const size_t go = (size_t)(kk + 1) * 32;
            CP16(sA + off, gA + go); CP16(sA + off + 16, gA + go + 8);
            CP16(sB + off, gB + go); CP16(sB + off + 16, gB + go + 8);
            CP_COMMIT();
            CP_WAIT(1);
        } else {
            CP_WAIT(0);
        }
        __syncthreads();
        const __nv_bfloat16* As = sm + (kk & 1) * STAGE_ELEMS;
        mma_tile(As, As + 5120, wm, wn, lane, f);
        __syncthreads();
    }

    // epilogue: j = i + c, guard 0 <= j < 1024; each output written once
    float* og = out + ((size_t)g << 20);
#pragma unroll
    for (int mi = 0; mi < 4; ++mi)
#pragma unroll
        for (int r = 0; r < 2; ++r) {
            const int i = i0 + wm + mi * 16 + (lane >> 2) + r * 8;
            float* orow = og + ((size_t)i << 10);
            const int jb = i + c0 + wn + ((lane & 3) << 1);
#pragma unroll
            for (int ni = 0; ni < 4; ++ni) {
                const int j0 = jb + ni * 8;
                const float x0 = f.c[mi][ni][r * 2];
                const float x1 = f.c[mi][ni][r * 2 + 1];
                if ((unsigned)j0 < 1024u)       orow[j0] = x0;
                if ((unsigned)(j0 + 1) < 1024u) orow[j0 + 1] = x1;
            }
        }
}

// ===================== launch ===============================================
extern "C" void kernel_launch(void* const* d_in, const int* in_sizes, int n_in,
                              void* d_out, int out_size) {
    const float* query = (const float*)d_in[0];
    const float* posem = (const float*)d_in[1];
    const float* dense = (const float*)d_in[2];
    float* out = (float*)d_out;
    (void)in_sizes; (void)n_in; (void)out_size;

    split_p<<<4096, 256>>>(posem);
    split_w<<<dim3(32, 32), dim3(32, 8)>>>(dense);
    split_q<<<4096, 256>>>(query);
    gemm1_mma<<<dim3(8, 16), 256, 2 * STAGE_BYTES>>>();
    gemm2_mma<<<dim3(9, 8, 32), 256, 2 * STAGE_BYTES>>>(out);
}

// round 5
// speedup vs baseline: 2.1038x; 1.0103x over previous
#include <cuda_runtime.h>
#include <cuda_bf16.h>
#include <cstdint>
#include <cstddef>

// ===================== portable tensor-core helpers (sm_80+) ================
__device__ __forceinline__ uint32_t smem_u32(const void* p) {
    uint32_t a;
    asm("{ .reg .u64 t; cvta.to.shared.u64 t, %1; cvt.u32.u64 %0, t; }"
        : "=r"(a) : "l"(p));
    return a;
}
#define CP16(sm, gp) \
    asm volatile("cp.async.cg.shared.global [%0], [%1], 16;" :: "r"(sm), "l"(gp))
#define CP_COMMIT() asm volatile("cp.async.commit_group;" ::: "memory")
#define CP_WAIT(n)  asm volatile("cp.async.wait_group %0;" :: "n"(n) : "memory")

#define LDSM_X4(r0, r1, r2, r3, addr) \
    asm volatile("ldmatrix.sync.aligned.m8n8.x4.shared.b16 {%0,%1,%2,%3}, [%4];" \
                 : "=r"(r0), "=r"(r1), "=r"(r2), "=r"(r3) : "r"(addr))
#define LDSM_X2(r0, r1, addr) \
    asm volatile("ldmatrix.sync.aligned.m8n8.x2.shared.b16 {%0,%1}, [%2];" \
                 : "=r"(r0), "=r"(r1) : "r"(addr))
#define MMA16816(c, a, b) \
    asm volatile("mma.sync.aligned.m16n8k16.row.col.f32.bf16.bf16.f32 " \
                 "{%0,%1,%2,%3}, {%4,%5,%6,%7}, {%8,%9}, {%0,%1,%2,%3};" \
                 : "+f"((c)[0]), "+f"((c)[1]), "+f"((c)[2]), "+f"((c)[3]) \
                 : "r"((a)[0]), "r"((a)[1]), "r"((a)[2]), "r"((a)[3]), \
                   "r"((b)[0]), "r"((b)[1]))

// ===================== scratch (bf16 split operands) ========================
// Pcat [2048][3072] : A' = [P_hi | P_hi | P_mid]           (row-major)
// Wt   [1024][3072] : B' = [W_hi | W_mid | W_hi]           (N-major)
// Qcat [32*1024][192] : per row [Q_hi | Q_hi | Q_mid]
// Rcat [16 he][2048 t][192] : per (he,t) [R_hi | R_mid | R_hi]
__device__ uint4 g_Pcat[786432];
__device__ uint4 g_Wt[393216];
__device__ uint4 g_Qcat[786432];
__device__ uint4 g_Rcat[786432];

// ===================== split kernels ========================================
__global__ void split_p(const float* __restrict__ P) {
    int idx = blockIdx.x * 256 + threadIdx.x;     // 2048 * 512
    int m = idx >> 9, kp = idx & 511;
    float2 v = make_float2(0.f, 0.f);
    if (m < 2047) v = *(const float2*)(P + (size_t)m * 1024 + 2 * kp);
    __nv_bfloat162 hi, mid;
    hi.x = __float2bfloat16(v.x); hi.y = __float2bfloat16(v.y);
    mid.x = __float2bfloat16(v.x - __bfloat162float(hi.x));
    mid.y = __float2bfloat16(v.y - __bfloat162float(hi.y));
    __nv_bfloat162* dst = (__nv_bfloat162*)g_Pcat + (size_t)m * 1536 + kp;
    dst[0] = hi; dst[512] = hi; dst[1024] = mid;
}

__global__ void split_q(const float* __restrict__ Q) {
    int idx = blockIdx.x * 256 + threadIdx.x;     // 32*1024 * 32
    int gi = idx >> 5, dp = idx & 31;
    float2 v = *(const float2*)(Q + (size_t)gi * 64 + 2 * dp);
    __nv_bfloat162 hi, mid;
    hi.x = __float2bfloat16(v.x); hi.y = __float2bfloat16(v.y);
    mid.x = __float2bfloat16(v.x - __bfloat162float(hi.x));
    mid.y = __float2bfloat16(v.y - __bfloat162float(hi.y));
    __nv_bfloat162* dst = (__nv_bfloat162*)g_Qcat + (size_t)gi * 96 + dp;
    dst[0] = hi; dst[32] = hi; dst[64] = mid;
}

__global__ void split_w(const float* __restrict__ W) {
    __shared__ float t[32][33];
    const int n0 = blockIdx.x * 32, k0 = blockIdx.y * 32;
    const int x = threadIdx.x, y = threadIdx.y;   // (32, 8)
    for (int r = 0; r < 32; r += 8)
        t[y + r][x] = W[(size_t)(k0 + y + r) * 1024 + n0 + x];
    __syncthreads();
    __nv_bfloat16* Wt = (__nv_bfloat16*)g_Wt;
    for (int r = 0; r < 32; r += 8) {
        const float v = t[x][y + r];              // W[k0+x][n0+y+r]
        const int n = n0 + y + r, k = k0 + x;
        const __nv_bfloat16 hi = __float2bfloat16(v);
        const __nv_bfloat16 mid = __float2bfloat16(v - __bfloat162float(hi));
        Wt[(size_t)n * 3072 + k] = hi;
        Wt[(size_t)n * 3072 + 1024 + k] = mid;
        Wt[(size_t)n * 3072 + 2048 + k] = hi;
    }
}

// ===================== common GEMM body =====================================
// CTA tile 128(M) x 128(N), BK=32, 256 threads = 8 warps (2x4),
// warp tile 64x32 via m16n8k16: 4 m-frags x 4 n-frags.
// Smem stage: A[128][40] + B[128][40] bf16 (40-pad => conflict-free ldmatrix).
// 4-stage cp.async ring, ONE __syncthreads per K-step:
//   barrier at iter kk proves all warps done with MMA(kk-1) => slot
//   (kk+3)%4 == (kk-1)%4 is free; loads issue BEFORE the MMA burst.
#define STAGE_ELEMS 10240          // bf16 elems per stage (A 5120 + B 5120)
#define STAGE_BYTES 20480
#define NSTAGE 4

struct Frag { float c[4][4][4]; };  // [mi][ni][4]

__device__ __forceinline__ void mma_tile(const __nv_bfloat16* As,
                                         const __nv_bfloat16* Bs,
                                         int wm, int wn, int lane, Frag& f) {
#pragma unroll
    for (int h = 0; h < 2; ++h) {
        const int k16 = h << 4;
        uint32_t a[4][4], b[4][2];
#pragma unroll
        for (int mi = 0; mi < 4; ++mi) {
            const uint32_t ad = smem_u32(
                As + (wm + mi * 16 + (lane & 15)) * 40 + k16 + ((lane >> 4) << 3));
            LDSM_X4(a[mi][0], a[mi][1], a[mi][2], a[mi][3], ad);
        }
#pragma unroll
        for (int ni = 0; ni < 4; ++ni) {
            const uint32_t bd = smem_u32(
                Bs + (wn + ni * 8 + (lane & 7)) * 40 + k16 + (((lane >> 3) & 1) << 3));
            LDSM_X2(b[ni][0], b[ni][1], bd);
        }
#pragma unroll
        for (int mi = 0; mi < 4; ++mi)
#pragma unroll
            for (int ni = 0; ni < 4; ++ni)
                MMA16816(f.c[mi][ni], a[mi], b[ni]);
    }
}

// ===================== GEMM1: R = P @ W  (M=2048,N=1024,K'=3072) ============
__global__ __launch_bounds__(256) void gemm1_mma() {
    extern __shared__ __nv_bfloat16 sm[];
    const int tid = threadIdx.x, lane = tid & 31, wid = tid >> 5;
    const int wm = (wid >> 2) << 6, wn = (wid & 3) << 5;
    const int m0 = blockIdx.y << 7, n0 = blockIdx.x << 7;

    const __nv_bfloat16* Ag = (const __nv_bfloat16*)g_Pcat;
    const __nv_bfloat16* Bg = (const __nv_bfloat16*)g_Wt;
    __nv_bfloat16* Rc = (__nv_bfloat16*)g_Rcat;

    const int lrow = tid >> 1, lch = (tid & 1) << 4;   // load row / 16-elem chunk
    const uint32_t sA = smem_u32(sm) + (uint32_t)(lrow * 40 + lch) * 2;
    const uint32_t sB = sA + STAGE_BYTES / 2;          // B at +10240 bytes
    const __nv_bfloat16* gA = Ag + (size_t)(m0 + lrow) * 3072 + lch;
    const __nv_bfloat16* gB = Bg + (size_t)(n0 + lrow) * 3072 + lch;

    const int NK = 96;
    // prologue: stages 0..2
#pragma unroll
    for (int s = 0; s < 3; ++s) {
        const uint32_t off = (uint32_t)(s * STAGE_BYTES);
        const size_t go = (size_t)s * 32;
        CP16(sA + off, gA + go); CP16(sA + off + 16, gA + go + 8);
        CP16(sB + off, gB + go); CP16(sB + off + 16, gB + go + 8);
        CP_COMMIT();
    }

    Frag f;
#pragma unroll
    for (int mi = 0; mi < 4; ++mi)
#pragma unroll
        for (int ni = 0; ni < 4; ++ni)
#pragma unroll
            for (int r = 0; r < 4; ++r) f.c[mi][ni][r] = 0.f;

    for (int kk = 0; kk < NK; ++kk) {
        CP_WAIT(2);                 // stage kk landed (<=2 groups outstanding)
        __syncthreads();            // all warps done reading slot (kk+3)%4
        if (kk + 3 < NK) {
            const uint32_t off = (uint32_t)(((kk + 3) & (NSTAGE - 1)) * STAGE_BYTES);
            const size_t go = (size_t)(kk + 3) * 32;
            CP16(sA + off, gA + go); CP16(sA + off + 16, gA + go + 8);
            CP16(sB + off, gB + go); CP16(sB + off + 16, gB + go + 8);
        }
        CP_COMMIT();                // unconditional: keeps group numbering
        const __nv_bfloat16* As = sm + (kk & (NSTAGE - 1)) * STAGE_ELEMS;
        mma_tile(As, As + 5120, wm, wn, lane, f);
    }

    // epilogue: fp32 accum -> bf16 hi/mid -> Rcat[he][m][split][64]
#pragma unroll
    for (int mi = 0; mi < 4; ++mi)
#pragma unroll
        for (int ni = 0; ni < 4; ++ni)
#pragma unroll
            for (int r = 0; r < 2; ++r) {
                const int m = m0 + wm + mi * 16 + (lane >> 2) + r * 8;
                const int n = n0 + wn + ni * 8 + ((lane & 3) << 1);
                const float x0 = f.c[mi][ni][r * 2];
                const float x1 = f.c[mi][ni][r * 2 + 1];
                __nv_bfloat162 hi, mid;
                hi.x = __float2bfloat16(x0); hi.y = __float2bfloat16(x1);
                mid.x = __float2bfloat16(x0 - __bfloat162float(hi.x));
                mid.y = __float2bfloat16(x1 - __bfloat162float(hi.y));
                const int he = n >> 6, d = n & 63;
                __nv_bfloat16* p = Rc + ((size_t)(he * 2048 + m)) * 192 + d;
                *(__nv_bfloat162*)(p)       = hi;
                *(__nv_bfloat162*)(p + 64)  = mid;
                *(__nv_bfloat162*)(p + 128) = hi;
            }
}

// ===================== GEMM2: banded score, diagonal form ===================
// out[g, i, i+c] = sum Qcat[g,i,:] . Rcat[he, 1023+c, :]   (K'=192)
__global__ __launch_bounds__(256) void gemm2_mma(float* __restrict__ out) {
    extern __shared__ __nv_bfloat16 sm[];
    const int tid = threadIdx.x, lane = tid & 31, wid = tid >> 5;
    const int wm = (wid >> 2) << 6, wn = (wid & 3) << 5;
    const int g = blockIdx.z, he = g >> 1;
    const int i0 = blockIdx.y << 7;
    const int c0 = ((int)blockIdx.x - 1) * 128 - i0;
    const int t0 = 1023 + c0;

    const __nv_bfloat16* Ag = (const __nv_bfloat16*)g_Qcat;
    const __nv_bfloat16* Bg = (const __nv_bfloat16*)g_Rcat;

    const int lrow = tid >> 1, lch = (tid & 1) << 4;
    const uint32_t sA = smem_u32(sm) + (uint32_t)(lrow * 40 + lch) * 2;
    const uint32_t sB = sA + STAGE_BYTES / 2;
    const __nv_bfloat16* gA = Ag + ((size_t)(g << 10) + i0 + lrow) * 192 + lch;
    int tr = t0 + lrow;                      // clamped rows feed only columns
    tr = tr < 0 ? 0 : (tr > 2046 ? 2046 : tr);   // whose j is out of range
    const __nv_bfloat16* gB = Bg + (size_t)(he * 2048 + tr) * 192 + lch;

    const int NK = 6;
#pragma unroll
    for (int s = 0; s < 3; ++s) {
        const uint32_t off = (uint32_t)(s * STAGE_BYTES);
        const size_t go = (size_t)s * 32;
        CP16(sA + off, gA + go); CP16(sA + off + 16, gA + go + 8);
        CP16(sB + off, gB + go); CP16(sB + off + 16, gB + go + 8);
        CP_COMMIT();
    }

    Frag f;
#pragma unroll
    for (int mi = 0; mi < 4; ++mi)
#pragma unroll
        for (int ni = 0; ni < 4; ++ni)
#pragma unroll
            for (int r = 0; r < 4; ++r) f.c[mi][ni][r] = 0.f;

#pragma unroll
    for (int kk = 0; kk < NK; ++kk) {
        CP_WAIT(2);
        __syncthreads();
        if (kk + 3 < NK) {
            const uint32_t off = (uint32_t)(((kk + 3) & (NSTAGE - 1)) * STAGE_BYTES);
            const size_t go = (size_t)(kk + 3) * 32;
            CP16(sA + off, gA + go); CP16(sA + off + 16, gA + go + 8);
            CP16(sB + off, gB + go); CP16(sB + off + 16, gB + go + 8);
        }
        CP_COMMIT();
        const __nv_bfloat16* As = sm + (kk & (NSTAGE - 1)) * STAGE_ELEMS;
        mma_tile(As, As + 5120, wm, wn, lane, f);
    }

    // epilogue: j = i + c, guard 0 <= j < 1024; each output written once
    float* og = out + ((size_t)g << 20);
#pragma unroll
    for (int mi = 0; mi < 4; ++mi)
#pragma unroll
        for (int r = 0; r < 2; ++r) {
            const int i = i0 + wm + mi * 16 + (lane >> 2) + r * 8;
            float* orow = og + ((size_t)i << 10);
            const int jb = i + c0 + wn + ((lane & 3) << 1);
#pragma unroll
            for (int ni = 0; ni < 4; ++ni) {
                const int j0 = jb + ni * 8;
                const float x0 = f.c[mi][ni][r * 2];
                const float x1 = f.c[mi][ni][r * 2 + 1];
                if ((unsigned)j0 < 1024u)       orow[j0] = x0;
                if ((unsigned)(j0 + 1) < 1024u) orow[j0 + 1] = x1;
            }
        }
}

// ===================== launch ===============================================
extern "C" void kernel_launch(void* const* d_in, const int* in_sizes, int n_in,
                              void* d_out, int out_size) {
    const float* query = (const float*)d_in[0];
    const float* posem = (const float*)d_in[1];
    const float* dense = (const float*)d_in[2];
    float* out = (float*)d_out;
    (void)in_sizes; (void)n_in; (void)out_size;

    cudaFuncSetAttribute(gemm1_mma, cudaFuncAttributeMaxDynamicSharedMemorySize,
                         NSTAGE * STAGE_BYTES);
    cudaFuncSetAttribute(gemm2_mma, cudaFuncAttributeMaxDynamicSharedMemorySize,
                         NSTAGE * STAGE_BYTES);

    split_p<<<4096, 256>>>(posem);
    split_w<<<dim3(32, 32), dim3(32, 8)>>>(dense);
    split_q<<<4096, 256>>>(query);
    gemm1_mma<<<dim3(8, 16), 256, NSTAGE * STAGE_BYTES>>>();
    gemm2_mma<<<dim3(9, 8, 32), 256, NSTAGE * STAGE_BYTES>>>(out);
}

// round 6
// speedup vs baseline: 2.4937x; 1.1853x over previous
#include <cuda_runtime.h>
#include <cuda_bf16.h>
#include <cstdint>
#include <cstddef>

// ===================== portable tensor-core helpers (sm_80+) ================
__device__ __forceinline__ uint32_t smem_u32(const void* p) {
    uint32_t a;
    asm("{ .reg .u64 t; cvta.to.shared.u64 t, %1; cvt.u32.u64 %0, t; }"
        : "=r"(a) : "l"(p));
    return a;
}
#define CP16(sm, gp) \
    asm volatile("cp.async.cg.shared.global [%0], [%1], 16;" :: "r"(sm), "l"(gp))
#define CP_COMMIT() asm volatile("cp.async.commit_group;" ::: "memory")
#define CP_WAIT(n)  asm volatile("cp.async.wait_group %0;" :: "n"(n) : "memory")

#define LDSM_X4(r0, r1, r2, r3, addr) \
    asm volatile("ldmatrix.sync.aligned.m8n8.x4.shared.b16 {%0,%1,%2,%3}, [%4];" \
                 : "=r"(r0), "=r"(r1), "=r"(r2), "=r"(r3) : "r"(addr))
#define LDSM_X2(r0, r1, addr) \
    asm volatile("ldmatrix.sync.aligned.m8n8.x2.shared.b16 {%0,%1}, [%2];" \
                 : "=r"(r0), "=r"(r1) : "r"(addr))
#define MMA16816(c, a, b) \
    asm volatile("mma.sync.aligned.m16n8k16.row.col.f32.bf16.bf16.f32 " \
                 "{%0,%1,%2,%3}, {%4,%5,%6,%7}, {%8,%9}, {%0,%1,%2,%3};" \
                 : "+f"((c)[0]), "+f"((c)[1]), "+f"((c)[2]), "+f"((c)[3]) \
                 : "r"((a)[0]), "r"((a)[1]), "r"((a)[2]), "r"((a)[3]), \
                   "r"((b)[0]), "r"((b)[1]))

// ===================== scratch (bf16 split operands) ========================
// Pcat [2048][3072] : A' = [P_hi | P_hi | P_mid]           (row-major)
// Wt   [1024][3072] : B' = [W_hi | W_mid | W_hi]           (N-major)
// Qcat [32*1024][192] : per row [Q_hi | Q_hi | Q_mid]
// Rcat [16 he][2048 t][192] : per (he,t) [R_hi | R_mid | R_hi]
__device__ uint4 g_Pcat[786432];
__device__ uint4 g_Wt[393216];
__device__ uint4 g_Qcat[786432];
__device__ uint4 g_Rcat[786432];

// ===================== split kernels ========================================
__global__ void split_p(const float* __restrict__ P) {
    int idx = blockIdx.x * 256 + threadIdx.x;     // 2048 * 512
    int m = idx >> 9, kp = idx & 511;
    float2 v = make_float2(0.f, 0.f);
    if (m < 2047) v = *(const float2*)(P + (size_t)m * 1024 + 2 * kp);
    __nv_bfloat162 hi, mid;
    hi.x = __float2bfloat16(v.x); hi.y = __float2bfloat16(v.y);
    mid.x = __float2bfloat16(v.x - __bfloat162float(hi.x));
    mid.y = __float2bfloat16(v.y - __bfloat162float(hi.y));
    __nv_bfloat162* dst = (__nv_bfloat162*)g_Pcat + (size_t)m * 1536 + kp;
    dst[0] = hi; dst[512] = hi; dst[1024] = mid;
}

__global__ void split_q(const float* __restrict__ Q) {
    int idx = blockIdx.x * 256 + threadIdx.x;     // 32*1024 * 32
    int gi = idx >> 5, dp = idx & 31;
    float2 v = *(const float2*)(Q + (size_t)gi * 64 + 2 * dp);
    __nv_bfloat162 hi, mid;
    hi.x = __float2bfloat16(v.x); hi.y = __float2bfloat16(v.y);
    mid.x = __float2bfloat16(v.x - __bfloat162float(hi.x));
    mid.y = __float2bfloat16(v.y - __bfloat162float(hi.y));
    __nv_bfloat162* dst = (__nv_bfloat162*)g_Qcat + (size_t)gi * 96 + dp;
    dst[0] = hi; dst[32] = hi; dst[64] = mid;
}

__global__ void split_w(const float* __restrict__ W) {
    __shared__ float t[32][33];
    const int n0 = blockIdx.x * 32, k0 = blockIdx.y * 32;
    const int x = threadIdx.x, y = threadIdx.y;   // (32, 8)
    for (int r = 0; r < 32; r += 8)
        t[y + r][x] = W[(size_t)(k0 + y + r) * 1024 + n0 + x];
    __syncthreads();
    __nv_bfloat16* Wt = (__nv_bfloat16*)g_Wt;
    for (int r = 0; r < 32; r += 8) {
        const float v = t[x][y + r];              // W[k0+x][n0+y+r]
        const int n = n0 + y + r, k = k0 + x;
        const __nv_bfloat16 hi = __float2bfloat16(v);
        const __nv_bfloat16 mid = __float2bfloat16(v - __bfloat162float(hi));
        Wt[(size_t)n * 3072 + k] = hi;
        Wt[(size_t)n * 3072 + 1024 + k] = mid;
        Wt[(size_t)n * 3072 + 2048 + k] = hi;
    }
}

// ===================== warp-tile MMA (32x32 per warp, one k16 slice) ========
// 512 threads = 16 warps, 4x4 warp grid over a 128x128 CTA tile.
struct Frag { float c[2][4][4]; };  // [mi][ni][4]

template <int STRIDE>
__device__ __forceinline__ void mma_k16(const __nv_bfloat16* As,
                                        const __nv_bfloat16* Bs,
                                        int wm, int wn, int lane, int k16,
                                        Frag& f) {
    uint32_t a[2][4], b[4][2];
#pragma unroll
    for (int mi = 0; mi < 2; ++mi) {
        const uint32_t ad = smem_u32(
            As + (wm + mi * 16 + (lane & 15)) * STRIDE + k16 + ((lane >> 4) << 3));
        LDSM_X4(a[mi][0], a[mi][1], a[mi][2], a[mi][3], ad);
    }
#pragma unroll
    for (int ni = 0; ni < 4; ++ni) {
        const uint32_t bd = smem_u32(
            Bs + (wn + ni * 8 + (lane & 7)) * STRIDE + k16 + (((lane >> 3) & 1) << 3));
        LDSM_X2(b[ni][0], b[ni][1], bd);
    }
#pragma unroll
    for (int mi = 0; mi < 2; ++mi)
#pragma unroll
        for (int ni = 0; ni < 4; ++ni)
            MMA16816(f.c[mi][ni], a[mi], b[ni]);
}

// ===================== GEMM1: R = P @ W  (M=2048,N=1024,K'=3072) ============
// 4-stage cp.async ring, one __syncthreads per 32-K step, 512 threads.
#define G1_STAGE_ELEMS 10240       // A 128x40 + B 128x40 bf16
#define G1_STAGE_BYTES 20480
#define NSTAGE 4

__global__ __launch_bounds__(512) void gemm1_mma() {
    extern __shared__ __nv_bfloat16 sm[];
    const int tid = threadIdx.x, lane = tid & 31, wid = tid >> 5;
    const int wm = (wid >> 2) << 5, wn = (wid & 3) << 5;
    const int m0 = blockIdx.y << 7, n0 = blockIdx.x << 7;

    const __nv_bfloat16* Ag = (const __nv_bfloat16*)g_Pcat;
    const __nv_bfloat16* Bg = (const __nv_bfloat16*)g_Wt;
    __nv_bfloat16* Rc = (__nv_bfloat16*)g_Rcat;

    // 512 threads: exactly one CP16 per operand per stage
    const int lrow = tid >> 2, lch = (tid & 3) << 3;
    const uint32_t sA = smem_u32(sm) + (uint32_t)(lrow * 40 + lch) * 2;
    const uint32_t sB = sA + G1_STAGE_BYTES / 2;
    const __nv_bfloat16* gA = Ag + (size_t)(m0 + lrow) * 3072 + lch;
    const __nv_bfloat16* gB = Bg + (size_t)(n0 + lrow) * 3072 + lch;

    const int NK = 96;
#pragma unroll
    for (int s = 0; s < 3; ++s) {
        const uint32_t off = (uint32_t)(s * G1_STAGE_BYTES);
        const size_t go = (size_t)s * 32;
        CP16(sA + off, gA + go);
        CP16(sB + off, gB + go);
        CP_COMMIT();
    }

    Frag f;
#pragma unroll
    for (int mi = 0; mi < 2; ++mi)
#pragma unroll
        for (int ni = 0; ni < 4; ++ni)
#pragma unroll
            for (int r = 0; r < 4; ++r) f.c[mi][ni][r] = 0.f;

    for (int kk = 0; kk < NK; ++kk) {
        CP_WAIT(2);                 // stage kk landed
        __syncthreads();            // all warps done reading slot (kk+3)%4
        if (kk + 3 < NK) {
            const uint32_t off = (uint32_t)(((kk + 3) & (NSTAGE - 1)) * G1_STAGE_BYTES);
            const size_t go = (size_t)(kk + 3) * 32;
            CP16(sA + off, gA + go);
            CP16(sB + off, gB + go);
        }
        CP_COMMIT();
        const __nv_bfloat16* As = sm + (kk & (NSTAGE - 1)) * G1_STAGE_ELEMS;
        mma_k16<40>(As, As + 5120, wm, wn, lane, 0, f);
        mma_k16<40>(As, As + 5120, wm, wn, lane, 16, f);
    }

    // epilogue: fp32 accum -> bf16 hi/mid -> Rcat[he][m][split][64]
#pragma unroll
    for (int mi = 0; mi < 2; ++mi)
#pragma unroll
        for (int ni = 0; ni < 4; ++ni)
#pragma unroll
            for (int r = 0; r < 2; ++r) {
                const int m = m0 + wm + mi * 16 + (lane >> 2) + r * 8;
                const int n = n0 + wn + ni * 8 + ((lane & 3) << 1);
                const float x0 = f.c[mi][ni][r * 2];
                const float x1 = f.c[mi][ni][r * 2 + 1];
                __nv_bfloat162 hi, mid;
                hi.x = __float2bfloat16(x0); hi.y = __float2bfloat16(x1);
                mid.x = __float2bfloat16(x0 - __bfloat162float(hi.x));
                mid.y = __float2bfloat16(x1 - __bfloat162float(hi.y));
                const int he = n >> 6, d = n & 63;
                __nv_bfloat16* p = Rc + ((size_t)(he * 2048 + m)) * 192 + d;
                *(__nv_bfloat162*)(p)       = hi;
                *(__nv_bfloat162*)(p + 64)  = mid;
                *(__nv_bfloat162*)(p + 128) = hi;
            }
}

// ===================== GEMM2: banded score, diagonal form ===================
// out[g, i, i+c] = sum Qcat[g,i,:] . Rcat[he, 1023+c, :]   (K'=192)
// K fully smem-resident: one cp.async burst, ONE barrier, 96 MMAs/warp burst.
#define G2_STRIDE 200               // 192 + 8 pad (conflict-free ldmatrix)
#define G2_ARR    25600             // 128 * 200 bf16 elems

__global__ __launch_bounds__(512) void gemm2_mma(float* __restrict__ out) {
    extern __shared__ __nv_bfloat16 sm[];
    const int tid = threadIdx.x, lane = tid & 31, wid = tid >> 5;
    const int wm = (wid >> 2) << 5, wn = (wid & 3) << 5;
    const int g = blockIdx.z, he = g >> 1;
    const int i0 = blockIdx.y << 7;
    const int c0 = ((int)blockIdx.x - 1) * 128 - i0;
    const int t0 = 1023 + c0;

    const __nv_bfloat16* Ag = (const __nv_bfloat16*)g_Qcat;
    const __nv_bfloat16* Bg = (const __nv_bfloat16*)g_Rcat;

    const int lrow = tid >> 2;                  // 0..127
    const int lc0 = (tid & 3) << 3;             // 0,8,16,24
    const uint32_t sA = smem_u32(sm) + (uint32_t)(lrow * G2_STRIDE) * 2;
    const uint32_t sB = sA + (uint32_t)G2_ARR * 2;
    const __nv_bfloat16* gA = Ag + ((size_t)(g << 10) + i0 + lrow) * 192;
    int tr = t0 + lrow;                         // clamped rows feed only
    tr = tr < 0 ? 0 : (tr > 2046 ? 2046 : tr);  // never-stored columns
    const __nv_bfloat16* gB = Bg + (size_t)(he * 2048 + tr) * 192;

    // load whole K' = 192: 6 chunks of 8 per thread per operand
#pragma unroll
    for (int c = 0; c < 6; ++c) {
        const int ko = lc0 + c * 32;
        CP16(sA + (uint32_t)ko * 2, gA + ko);
        CP16(sB + (uint32_t)ko * 2, gB + ko);
    }
    CP_COMMIT();

    Frag f;
#pragma unroll
    for (int mi = 0; mi < 2; ++mi)
#pragma unroll
        for (int ni = 0; ni < 4; ++ni)
#pragma unroll
            for (int r = 0; r < 4; ++r) f.c[mi][ni][r] = 0.f;

    CP_WAIT(0);
    __syncthreads();

    const __nv_bfloat16* As = sm;
    const __nv_bfloat16* Bs = sm + G2_ARR;
#pragma unroll
    for (int ks = 0; ks < 12; ++ks)
        mma_k16<G2_STRIDE>(As, Bs, wm, wn, lane, ks << 4, f);

    // epilogue: j = i + c, guard 0 <= j < 1024; each output written once
    float* og = out + ((size_t)g << 20);
#pragma unroll
    for (int mi = 0; mi < 2; ++mi)
#pragma unroll
        for (int r = 0; r < 2; ++r) {
            const int i = i0 + wm + mi * 16 + (lane >> 2) + r * 8;
            float* orow = og + ((size_t)i << 10);
            const int jb = i + c0 + wn + ((lane & 3) << 1);
#pragma unroll
            for (int ni = 0; ni < 4; ++ni) {
                const int j0 = jb + ni * 8;
                const float x0 = f.c[mi][ni][r * 2];
                const float x1 = f.c[mi][ni][r * 2 + 1];
                if ((unsigned)j0 < 1024u)       orow[j0] = x0;
                if ((unsigned)(j0 + 1) < 1024u) orow[j0 + 1] = x1;
            }
        }
}

// ===================== launch ===============================================
extern "C" void kernel_launch(void* const* d_in, const int* in_sizes, int n_in,
                              void* d_out, int out_size) {
    const float* query = (const float*)d_in[0];
    const float* posem = (const float*)d_in[1];
    const float* dense = (const float*)d_in[2];
    float* out = (float*)d_out;
    (void)in_sizes; (void)n_in; (void)out_size;

    cudaFuncSetAttribute(gemm1_mma, cudaFuncAttributeMaxDynamicSharedMemorySize,
                         NSTAGE * G1_STAGE_BYTES);
    cudaFuncSetAttribute(gemm2_mma, cudaFuncAttributeMaxDynamicSharedMemorySize,
                         2 * G2_ARR * 2);

    split_p<<<4096, 256>>>(posem);
    split_w<<<dim3(32, 32), dim3(32, 8)>>>(dense);
    split_q<<<4096, 256>>>(query);
    gemm1_mma<<<dim3(8, 16), 512, NSTAGE * G1_STAGE_BYTES>>>();
    gemm2_mma<<<dim3(9, 8, 32), 512, 2 * G2_ARR * 2>>>(out);
}